// round 12
// baseline (speedup 1.0000x reference)
#include <cuda_runtime.h>
#include <cuda_bf16.h>

// WTA / row-wise top-k(=64) scatter-to-dense, exact incl. stable tie-breaking.
// 1 CTA per row (TPB=512), row as raw floats in registers (4x float4).
// Fast path (valid when count(f>=2.0) >= k; 9-sigma certain for N(0,1) rows):
//   (1) fused 128-bin histogram of (bits>>17)-0x4000 over f >= 2.0 with
//       per-bin slot capture of full bits ([2,6) spans 96 consecutive bins;
//       >=6 clamps to bin 127 and is resolved exactly by the rank step)
//   (2) warp0: pick bin where reverse-cumulative crosses k (4-chunk suffix
//       scan), then rank the E (expected ~3, dynamically bounded) captured
//       elements with a shuffle loop -> exact k-th value + tie metadata
//   (3) output: out = (f >= thr) ? f : 0 ; rare stable tie-break by column.
// Generic fallback (cold, exact): 4-pass 256-bin radix select over fmap keys.

#define COLS  8192
#define TPB   512
#define VPT   4                    // float4 per thread -> 16 scalars
#define NW    (TPB / 32)
#define NBIN  128
#define SLOTS 16
#define FULL  0xffffffffu

__device__ __forceinline__ unsigned fmap_u(unsigned b) {
    return b ^ ((unsigned)((int)b >> 31) | 0x80000000u);
}
__device__ __forceinline__ float funmap(unsigned v) {
    unsigned mask = ((unsigned)((int)(~v) >> 31)) | 0x80000000u;
    return __uint_as_float(v ^ mask);
}

__global__ __launch_bounds__(TPB, 4)
void wta_topk_kernel(const float4* __restrict__ x4,
                     const int*    __restrict__ kp,
                     float4*       __restrict__ o4)
{
    __shared__ unsigned sHist[256];          // fast path uses [0,128)
    __shared__ unsigned sBin[NBIN * SLOTS];
    __shared__ unsigned sWsum[NW];
    __shared__ unsigned sSel, sNeed, sEq, sThr, sFlag;

    const int tid  = threadIdx.x;
    const int lane = tid & 31;
    const int warp = tid >> 5;
    const size_t base = (size_t)blockIdx.x * (COLS / 4) + tid;

    // ---- load row (raw floats) ----
    float4 v[VPT];
#pragma unroll
    for (int j = 0; j < VPT; j++)
        v[j] = __ldcs(&x4[base + (size_t)j * TPB]);
    const unsigned k = (unsigned)__ldg(kp);

    if (tid < NBIN) sHist[tid] = 0u;
    if (tid == 0) sFlag = 0u;
    __syncthreads();                                              // S1

    // ---- (1) fused 128-bin histogram + slot capture over f >= 2.0 ----
#pragma unroll
    for (int j = 0; j < VPT; j++) {
#pragma unroll
        for (int c = 0; c < 4; c++) {
            const float f = (c == 0) ? v[j].x : (c == 1) ? v[j].y
                          : (c == 2) ? v[j].z : v[j].w;
            if (f >= 2.0f) {
                const unsigned bits = __float_as_uint(f);
                unsigned b = (bits >> 17) - 0x4000u;   // 2.0 -> bin 0
                b = min(b, 127u);
                const unsigned p = atomicAdd(&sHist[b], 1u);
                if (p < SLOTS) sBin[(b << 4) + p] = bits;
            }
        }
    }
    __syncthreads();                                              // S2

    // ---- (2) warp0: bin select (4 chunks) + dynamic shuffle rank ----
    if (warp == 0) {
        unsigned hv4[4], tot[4];
#pragma unroll
        for (int c = 0; c < 4; c++) {
            hv4[c] = sHist[c * 32 + lane];
            tot[c] = __reduce_add_sync(FULL, hv4[c]);
        }
        unsigned suf = 0u, tch = 0u, exC = 0u;
#pragma unroll
        for (int c = 3; c >= 0; c--) {
            if (suf < k && k <= suf + tot[c]) { tch = (unsigned)c; exC = suf; }
            suf += tot[c];
        }
        if (suf < k) {
            if (lane == 0) sFlag = 1u;
        } else {
            const unsigned hv = hv4[tch];
            unsigned incl = hv;            // suffix sum over higher bins
#pragma unroll
            for (int o = 1; o < 32; o <<= 1) {
                const unsigned n = __shfl_down_sync(FULL, incl, o);
                if (lane + o < 32) incl += n;
            }
            const unsigned excl = incl - hv;
            const bool fired = (exC + excl < k) && (k <= exC + incl);
            const unsigned fm = __ballot_sync(FULL, fired);
            const int src = __ffs(fm) - 1;
            const unsigned selBin = tch * 32u + (unsigned)src;
            const unsigned need1  = k - exC - __shfl_sync(FULL, excl, src);
            const unsigned E      = __shfl_sync(FULL, hv, src);
            if (E > SLOTS) {
                if (lane == 0) sFlag = 1u;
            } else {
                // exact rank among E captured keys (loop bounded by E,
                // warp-uniform, expected ~3). Positive-float bits compare
                // identically to values.
                const unsigned key = (lane < (int)E)
                                   ? sBin[(selBin << 4) + lane] : 0u;
                unsigned gt = 0u, eq = 0u;
                for (int o = 0; o < (int)E; o++) {
                    const unsigned other = __shfl_sync(FULL, key, o);
                    gt += (other > key) ? 1u : 0u;
                    eq += (other == key) ? 1u : 0u;
                }
                if (lane < (int)E && gt < need1 && need1 <= gt + eq) {
                    sThr  = key;            // unique key value fires
                    sNeed = need1 - gt;
                    sEq   = eq;
                }
            }
        }
    }
    __syncthreads();                                              // S3

    float thrF;
    unsigned need, eqCnt;
    if (sFlag == 0u) {
        thrF  = __uint_as_float(sThr);
        need  = sNeed;
        eqCnt = sEq;
    } else {
        // ---- generic fallback: 4-pass 256-bin radix over fmap keys ----
        unsigned prefix = 0u;
        need = k;
#pragma unroll 1
        for (int p = 3; p >= 0; p--) {
            const int sh = 8 * p;
            __syncthreads();
            if (tid < 256) sHist[tid] = 0u;
            __syncthreads();
#pragma unroll 1
            for (int j = 0; j < VPT; j++) {
                const float e[4] = { v[j].x, v[j].y, v[j].z, v[j].w };
#pragma unroll
                for (int c = 0; c < 4; c++) {
                    const unsigned key = fmap_u(__float_as_uint(e[c]));
                    const bool m = (p == 3) || (((key ^ prefix) >> (sh + 8)) == 0u);
                    if (m) atomicAdd(&sHist[(key >> sh) & 255u], 1u);
                }
            }
            __syncthreads();
            if (warp == 0) {
                unsigned hv8[8], tot[8];
#pragma unroll
                for (int c = 0; c < 8; c++) {
                    hv8[c] = sHist[c * 32 + lane];
                    tot[c] = __reduce_add_sync(FULL, hv8[c]);
                }
                unsigned suf = 0u, tch = 0u, exC = 0u;
#pragma unroll
                for (int c = 7; c >= 0; c--) {
                    if (suf < need && need <= suf + tot[c]) { tch = (unsigned)c; exC = suf; }
                    suf += tot[c];
                }
                const unsigned hv = hv8[tch];
                unsigned incl = hv;
#pragma unroll
                for (int o = 1; o < 32; o <<= 1) {
                    const unsigned n = __shfl_down_sync(FULL, incl, o);
                    if (lane + o < 32) incl += n;
                }
                const unsigned excl = incl - hv;
                if (exC + excl < need && need <= exC + incl) {
                    sSel  = tch * 32 + (unsigned)lane;
                    sNeed = need - exC - excl;
                    sEq   = hv;
                }
            }
            __syncthreads();
            prefix |= sSel << sh;
            need   = sNeed;
        }
        eqCnt = sEq;
        thrF  = funmap(prefix);
    }

    // ---- (3) output ----
    if (need == eqCnt) {
        // common path: keep all f >= thrF
#pragma unroll
        for (int j = 0; j < VPT; j++) {
            float4 o;
            o.x = (v[j].x >= thrF) ? v[j].x : 0.0f;
            o.y = (v[j].y >= thrF) ? v[j].y : 0.0f;
            o.z = (v[j].z >= thrF) ? v[j].z : 0.0f;
            o.w = (v[j].w >= thrF) ? v[j].w : 0.0f;
            __stcs(&o4[base + (size_t)j * TPB], o);
        }
    } else {
        // rare: stable tie-break, keep first `need` of ==thrF by column order
        unsigned keepMask = 0u, running = 0u;
#pragma unroll 1
        for (int j = 0; j < VPT; j++) {
            const float e[4] = { v[j].x, v[j].y, v[j].z, v[j].w };
            unsigned eq[4], lc = 0u;
#pragma unroll
            for (int c = 0; c < 4; c++) {
                eq[c] = (e[c] == thrF) ? 1u : 0u;
                lc += eq[c];
            }
            unsigned pre = lc;
#pragma unroll
            for (int o = 1; o < 32; o <<= 1) {
                const unsigned n = __shfl_up_sync(FULL, pre, o);
                if (lane >= o) pre += n;
            }
            const unsigned excl = pre - lc;
            __syncthreads();
            if (lane == 31) sWsum[warp] = pre;
            __syncthreads();
            unsigned off = 0u, tot = 0u;
#pragma unroll
            for (int w = 0; w < NW; w++) {
                const unsigned t = sWsum[w];
                if (w < warp) off += t;
                tot += t;
            }
            unsigned r = running + off + excl;
#pragma unroll
            for (int c = 0; c < 4; c++) {
                if (eq[c]) {
                    if (r < need) keepMask |= 1u << (4 * j + c);
                    r++;
                }
            }
            running += tot;
        }
#pragma unroll
        for (int j = 0; j < VPT; j++) {
            const float e[4] = { v[j].x, v[j].y, v[j].z, v[j].w };
            float o[4];
#pragma unroll
            for (int c = 0; c < 4; c++) {
                const int i = 4 * j + c;
                const bool keep = (e[c] > thrF) ||
                                  ((e[c] == thrF) && ((keepMask >> i) & 1u));
                o[c] = keep ? e[c] : 0.0f;
            }
            float4 ov = { o[0], o[1], o[2], o[3] };
            __stcs(&o4[base + (size_t)j * TPB], ov);
        }
    }
}

extern "C" void kernel_launch(void* const* d_in, const int* in_sizes, int n_in,
                              void* d_out, int out_size) {
    const float4* x4 = (const float4*)d_in[0];
    const int*    kp = (const int*)d_in[1];
    float4*       o4 = (float4*)d_out;
    const int rows = in_sizes[0] / COLS;
    wta_topk_kernel<<<rows, TPB>>>(x4, kp, o4);
}

// round 13
// speedup vs baseline: 2.1887x; 2.1887x over previous
#include <cuda_runtime.h>
#include <cuda_bf16.h>

// WTA / row-wise top-k(=64) scatter-to-dense, exact incl. stable tie-breaking.
// 1 CTA per row (TPB=512), row as raw floats in registers (4x float4).
// Fast path (valid when count(f>=2.0) >= k; 9-sigma certain for N(0,1) rows):
//   (1) fused 128-bin histogram of (bits>>17)-0x2000 over f >= 2.0 with
//       per-bin slot capture of full bits ([2,6) spans bins 0..95;
//       >=6 clamps to bin 127 and is resolved exactly by the rank step)
//   (2) warp0: pick bin where reverse-cumulative crosses k (4-chunk suffix
//       scan), then rank the E (expected ~3, dynamically bounded) captured
//       elements with a shuffle loop -> exact k-th value + tie metadata
//   (3) output: out = (f >= thr) ? f : 0 ; rare stable tie-break by column.
// Generic fallback (cold, exact): 4-pass 256-bin radix select over fmap keys.

#define COLS  8192
#define TPB   512
#define VPT   4                    // float4 per thread -> 16 scalars
#define NW    (TPB / 32)
#define NBIN  128
#define SLOTS 16
#define FULL  0xffffffffu

__device__ __forceinline__ unsigned fmap_u(unsigned b) {
    return b ^ ((unsigned)((int)b >> 31) | 0x80000000u);
}
__device__ __forceinline__ float funmap(unsigned v) {
    unsigned mask = ((unsigned)((int)(~v) >> 31)) | 0x80000000u;
    return __uint_as_float(v ^ mask);
}

__global__ __launch_bounds__(TPB, 4)
void wta_topk_kernel(const float4* __restrict__ x4,
                     const int*    __restrict__ kp,
                     float4*       __restrict__ o4)
{
    __shared__ unsigned sHist[256];          // fast path uses [0,128)
    __shared__ unsigned sBin[NBIN * SLOTS];
    __shared__ unsigned sWsum[NW];
    __shared__ unsigned sSel, sNeed, sEq, sThr, sFlag;

    const int tid  = threadIdx.x;
    const int lane = tid & 31;
    const int warp = tid >> 5;
    const size_t base = (size_t)blockIdx.x * (COLS / 4) + tid;

    // ---- load row (raw floats) ----
    float4 v[VPT];
#pragma unroll
    for (int j = 0; j < VPT; j++)
        v[j] = __ldcs(&x4[base + (size_t)j * TPB]);
    const unsigned k = (unsigned)__ldg(kp);

    if (tid < NBIN) sHist[tid] = 0u;
    if (tid == 0) sFlag = 0u;
    __syncthreads();                                              // S1

    // ---- (1) fused 128-bin histogram + slot capture over f >= 2.0 ----
#pragma unroll
    for (int j = 0; j < VPT; j++) {
#pragma unroll
        for (int c = 0; c < 4; c++) {
            const float f = (c == 0) ? v[j].x : (c == 1) ? v[j].y
                          : (c == 2) ? v[j].z : v[j].w;
            if (f >= 2.0f) {
                const unsigned bits = __float_as_uint(f);
                unsigned b = (bits >> 17) - 0x2000u;   // 2.0 -> bin 0
                b = min(b, 127u);
                const unsigned p = atomicAdd(&sHist[b], 1u);
                if (p < SLOTS) sBin[(b << 4) + p] = bits;
            }
        }
    }
    __syncthreads();                                              // S2

    // ---- (2) warp0: bin select (4 chunks) + dynamic shuffle rank ----
    if (warp == 0) {
        unsigned hv4[4], tot[4];
#pragma unroll
        for (int c = 0; c < 4; c++) {
            hv4[c] = sHist[c * 32 + lane];
            tot[c] = __reduce_add_sync(FULL, hv4[c]);
        }
        unsigned suf = 0u, tch = 0u, exC = 0u;
#pragma unroll
        for (int c = 3; c >= 0; c--) {
            if (suf < k && k <= suf + tot[c]) { tch = (unsigned)c; exC = suf; }
            suf += tot[c];
        }
        if (suf < k) {
            if (lane == 0) sFlag = 1u;
        } else {
            const unsigned hv = hv4[tch];
            unsigned incl = hv;            // suffix sum over higher bins
#pragma unroll
            for (int o = 1; o < 32; o <<= 1) {
                const unsigned n = __shfl_down_sync(FULL, incl, o);
                if (lane + o < 32) incl += n;
            }
            const unsigned excl = incl - hv;
            const bool fired = (exC + excl < k) && (k <= exC + incl);
            const unsigned fm = __ballot_sync(FULL, fired);
            const int src = __ffs(fm) - 1;
            const unsigned selBin = tch * 32u + (unsigned)src;
            const unsigned need1  = k - exC - __shfl_sync(FULL, excl, src);
            const unsigned E      = __shfl_sync(FULL, hv, src);
            if (E > SLOTS) {
                if (lane == 0) sFlag = 1u;
            } else {
                // exact rank among E captured keys (loop bounded by E,
                // warp-uniform, expected ~3). Positive-float bits compare
                // identically to values.
                const unsigned key = (lane < (int)E)
                                   ? sBin[(selBin << 4) + lane] : 0u;
                unsigned gt = 0u, eq = 0u;
                for (int o = 0; o < (int)E; o++) {
                    const unsigned other = __shfl_sync(FULL, key, o);
                    gt += (other > key) ? 1u : 0u;
                    eq += (other == key) ? 1u : 0u;
                }
                if (lane < (int)E && gt < need1 && need1 <= gt + eq) {
                    sThr  = key;            // unique key value fires
                    sNeed = need1 - gt;
                    sEq   = eq;
                }
            }
        }
    }
    __syncthreads();                                              // S3

    float thrF;
    unsigned need, eqCnt;
    if (sFlag == 0u) {
        thrF  = __uint_as_float(sThr);
        need  = sNeed;
        eqCnt = sEq;
    } else {
        // ---- generic fallback: 4-pass 256-bin radix over fmap keys ----
        unsigned prefix = 0u;
        need = k;
#pragma unroll 1
        for (int p = 3; p >= 0; p--) {
            const int sh = 8 * p;
            __syncthreads();
            if (tid < 256) sHist[tid] = 0u;
            __syncthreads();
#pragma unroll 1
            for (int j = 0; j < VPT; j++) {
                const float e[4] = { v[j].x, v[j].y, v[j].z, v[j].w };
#pragma unroll
                for (int c = 0; c < 4; c++) {
                    const unsigned key = fmap_u(__float_as_uint(e[c]));
                    const bool m = (p == 3) || (((key ^ prefix) >> (sh + 8)) == 0u);
                    if (m) atomicAdd(&sHist[(key >> sh) & 255u], 1u);
                }
            }
            __syncthreads();
            if (warp == 0) {
                unsigned hv8[8], tot[8];
#pragma unroll
                for (int c = 0; c < 8; c++) {
                    hv8[c] = sHist[c * 32 + lane];
                    tot[c] = __reduce_add_sync(FULL, hv8[c]);
                }
                unsigned suf = 0u, tch = 0u, exC = 0u;
#pragma unroll
                for (int c = 7; c >= 0; c--) {
                    if (suf < need && need <= suf + tot[c]) { tch = (unsigned)c; exC = suf; }
                    suf += tot[c];
                }
                const unsigned hv = hv8[tch];
                unsigned incl = hv;
#pragma unroll
                for (int o = 1; o < 32; o <<= 1) {
                    const unsigned n = __shfl_down_sync(FULL, incl, o);
                    if (lane + o < 32) incl += n;
                }
                const unsigned excl = incl - hv;
                if (exC + excl < need && need <= exC + incl) {
                    sSel  = tch * 32 + (unsigned)lane;
                    sNeed = need - exC - excl;
                    sEq   = hv;
                }
            }
            __syncthreads();
            prefix |= sSel << sh;
            need   = sNeed;
        }
        eqCnt = sEq;
        thrF  = funmap(prefix);
    }

    // ---- (3) output ----
    if (need == eqCnt) {
        // common path: keep all f >= thrF
#pragma unroll
        for (int j = 0; j < VPT; j++) {
            float4 o;
            o.x = (v[j].x >= thrF) ? v[j].x : 0.0f;
            o.y = (v[j].y >= thrF) ? v[j].y : 0.0f;
            o.z = (v[j].z >= thrF) ? v[j].z : 0.0f;
            o.w = (v[j].w >= thrF) ? v[j].w : 0.0f;
            __stcs(&o4[base + (size_t)j * TPB], o);
        }
    } else {
        // rare: stable tie-break, keep first `need` of ==thrF by column order
        unsigned keepMask = 0u, running = 0u;
#pragma unroll 1
        for (int j = 0; j < VPT; j++) {
            const float e[4] = { v[j].x, v[j].y, v[j].z, v[j].w };
            unsigned eq[4], lc = 0u;
#pragma unroll
            for (int c = 0; c < 4; c++) {
                eq[c] = (e[c] == thrF) ? 1u : 0u;
                lc += eq[c];
            }
            unsigned pre = lc;
#pragma unroll
            for (int o = 1; o < 32; o <<= 1) {
                const unsigned n = __shfl_up_sync(FULL, pre, o);
                if (lane >= o) pre += n;
            }
            const unsigned excl = pre - lc;
            __syncthreads();
            if (lane == 31) sWsum[warp] = pre;
            __syncthreads();
            unsigned off = 0u, tot = 0u;
#pragma unroll
            for (int w = 0; w < NW; w++) {
                const unsigned t = sWsum[w];
                if (w < warp) off += t;
                tot += t;
            }
            unsigned r = running + off + excl;
#pragma unroll
            for (int c = 0; c < 4; c++) {
                if (eq[c]) {
                    if (r < need) keepMask |= 1u << (4 * j + c);
                    r++;
                }
            }
            running += tot;
        }
#pragma unroll
        for (int j = 0; j < VPT; j++) {
            const float e[4] = { v[j].x, v[j].y, v[j].z, v[j].w };
            float o[4];
#pragma unroll
            for (int c = 0; c < 4; c++) {
                const int i = 4 * j + c;
                const bool keep = (e[c] > thrF) ||
                                  ((e[c] == thrF) && ((keepMask >> i) & 1u));
                o[c] = keep ? e[c] : 0.0f;
            }
            float4 ov = { o[0], o[1], o[2], o[3] };
            __stcs(&o4[base + (size_t)j * TPB], ov);
        }
    }
}

extern "C" void kernel_launch(void* const* d_in, const int* in_sizes, int n_in,
                              void* d_out, int out_size) {
    const float4* x4 = (const float4*)d_in[0];
    const int*    kp = (const int*)d_in[1];
    float4*       o4 = (float4*)d_out;
    const int rows = in_sizes[0] / COLS;
    wta_topk_kernel<<<rows, TPB>>>(x4, kp, o4);
}